// round 5
// baseline (speedup 1.0000x reference)
#include <cuda_runtime.h>

// E8 quantizer, closed form, f32x2-packed (2 points per thread).
//
// Math (see earlier rounds): all 240 E8 roots have ||c||^2 = 2 so the softmax
// reduces to softmax(beta * x.c), beta = 2/0.3, which factorizes:
//  Type-1 (112): A_i = 2cosh(beta x_i), B_i = 2sinh(beta x_i)
//     denom += sum_{i<j} A_i A_j,  num_d = B_d * exclSum_d(A)
//  Type-2 (128, even parity): a_i = 2cosh(beta x_i/2), b_i = 2sinh(beta x_i/2)
//     denom += (prod a + prod b)/2,  num_d = (b_d exclProd_d(a) + a_d exclProd_d(b))/4
//  A = a^2 - 2, B = a*b  -> 16 EX2 + 1 RCP per point.
// Exclusive sums/products via binary tree: all-positive adds / sign-safe muls,
// no cancellation. Roots in +- pairs => denom >= 1, no max-shift needed.
//
// This round: Blackwell packed f32x2 FMA pipe (FFMA2, PTX-only) — two points
// packed lane-wise into 64-bit regs halves the FMA-pipe issue count. Points
// p and p + N/2 keep both streams fully coalesced (R2 lesson). Persistent
// single-wave grid + grid-stride (R4 winner). 128-reg clamp, watch for spills.

#define BETA_HALF_LOG2E 4.8089834696568576f   // (2/0.3)/2 * log2(e)

typedef unsigned long long u64;

__device__ __forceinline__ float ex2_approx(float x) {
    float y; asm("ex2.approx.ftz.f32 %0, %1;" : "=f"(y) : "f"(x)); return y;
}
__device__ __forceinline__ float rcp_approx(float x) {
    float y; asm("rcp.approx.ftz.f32 %0, %1;" : "=f"(y) : "f"(x)); return y;
}
__device__ __forceinline__ u64 pk(float lo, float hi) {
    u64 r; asm("mov.b64 %0, {%1, %2};" : "=l"(r) : "f"(lo), "f"(hi)); return r;
}
__device__ __forceinline__ void upk(float& lo, float& hi, u64 v) {
    asm("mov.b64 {%0, %1}, %2;" : "=f"(lo), "=f"(hi) : "l"(v));
}
__device__ __forceinline__ u64 f2fma(u64 a, u64 b, u64 c) {
    u64 r; asm("fma.rn.f32x2 %0, %1, %2, %3;" : "=l"(r) : "l"(a), "l"(b), "l"(c)); return r;
}
__device__ __forceinline__ u64 f2add(u64 a, u64 b) {
    u64 r; asm("add.rn.f32x2 %0, %1, %2;" : "=l"(r) : "l"(a), "l"(b)); return r;
}
__device__ __forceinline__ u64 f2mul(u64 a, u64 b) {
    u64 r; asm("mul.rn.f32x2 %0, %1, %2;" : "=l"(r) : "l"(a), "l"(b)); return r;
}

__global__ void __launch_bounds__(256, 2) e8_quantize_kernel(
    const float4* __restrict__ x4, float4* __restrict__ o4, int n, int M, int stride)
{
    const u64 cM1 = pk(-1.0f, -1.0f);
    const u64 cN2 = pk(-2.0f, -2.0f);
    const u64 cQ  = pk(0.25f, 0.25f);
    const u64 cH  = pk(0.5f, 0.5f);

    for (int t = blockIdx.x * blockDim.x + threadIdx.x; t < M; t += stride) {
        int p = t;
        int qr = t + M;
        int q  = (qr < n) ? qr : p;       // odd-n guard: duplicate (same data, same addr)

        float4 u0 = x4[2 * p + 0];
        float4 u1 = x4[2 * p + 1];
        float4 w0 = x4[2 * q + 0];
        float4 w1 = x4[2 * q + 1];

        float xp[8] = {u0.x, u0.y, u0.z, u0.w, u1.x, u1.y, u1.z, u1.w};
        float xq[8] = {w0.x, w0.y, w0.z, w0.w, w1.x, w1.y, w1.z, w1.w};

        u64 a[8], b[8], A[8];
#pragma unroll
        for (int i = 0; i < 8; i++) {
            float tp = xp[i] * BETA_HALF_LOG2E;
            float tq = xq[i] * BETA_HALF_LOG2E;
            u64 hp = pk(ex2_approx(tp),  ex2_approx(tq));
            u64 hn = pk(ex2_approx(-tp), ex2_approx(-tq));
            a[i] = f2add(hp, hn);
            b[i] = f2fma(hn, cM1, hp);       // hp - hn
            A[i] = f2fma(a[i], a[i], cN2);   // a^2 - 2 = 2cosh(beta x)
        }

        // ---- exclusive sums of A via tree (all positive) ----
        u64 s01 = f2add(A[0], A[1]), s23 = f2add(A[2], A[3]);
        u64 s45 = f2add(A[4], A[5]), s67 = f2add(A[6], A[7]);
        u64 s0123 = f2add(s01, s23), s4567 = f2add(s45, s67);
        u64 ES01 = f2add(s4567, s23), ES23 = f2add(s4567, s01);
        u64 ES45 = f2add(s0123, s67), ES67 = f2add(s0123, s45);
        u64 eS[8];
        eS[0] = f2add(ES01, A[1]); eS[1] = f2add(ES01, A[0]);
        eS[2] = f2add(ES23, A[3]); eS[3] = f2add(ES23, A[2]);
        eS[4] = f2add(ES45, A[5]); eS[5] = f2add(ES45, A[4]);
        eS[6] = f2add(ES67, A[7]); eS[7] = f2add(ES67, A[6]);

        // D1 = 0.5 * sum_d A_d * eS_d
        u64 D1 = f2mul(A[0], eS[0]);
#pragma unroll
        for (int d = 1; d < 8; d++) D1 = f2fma(A[d], eS[d], D1);

        // ---- exclusive products of a (0.25 folded into tree root) ----
        u64 ma01 = f2mul(a[0], a[1]), ma23 = f2mul(a[2], a[3]);
        u64 ma45 = f2mul(a[4], a[5]), ma67 = f2mul(a[6], a[7]);
        u64 ma0123 = f2mul(ma01, ma23), ma4567 = f2mul(ma45, ma67);
        u64 Pa = f2mul(ma0123, ma4567);
        u64 EA0123 = f2mul(ma4567, cQ), EA4567 = f2mul(ma0123, cQ);
        u64 EA01 = f2mul(EA0123, ma23), EA23 = f2mul(EA0123, ma01);
        u64 EA45 = f2mul(EA4567, ma67), EA67 = f2mul(EA4567, ma45);
        u64 ea[8];
        ea[0] = f2mul(EA01, a[1]); ea[1] = f2mul(EA01, a[0]);
        ea[2] = f2mul(EA23, a[3]); ea[3] = f2mul(EA23, a[2]);
        ea[4] = f2mul(EA45, a[5]); ea[5] = f2mul(EA45, a[4]);
        ea[6] = f2mul(EA67, a[7]); ea[7] = f2mul(EA67, a[6]);

        // ---- exclusive products of b (0.25 folded) ----
        u64 mb01 = f2mul(b[0], b[1]), mb23 = f2mul(b[2], b[3]);
        u64 mb45 = f2mul(b[4], b[5]), mb67 = f2mul(b[6], b[7]);
        u64 mb0123 = f2mul(mb01, mb23), mb4567 = f2mul(mb45, mb67);
        u64 Pb = f2mul(mb0123, mb4567);
        u64 EB0123 = f2mul(mb4567, cQ), EB4567 = f2mul(mb0123, cQ);
        u64 EB01 = f2mul(EB0123, mb23), EB23 = f2mul(EB0123, mb01);
        u64 EB45 = f2mul(EB4567, mb67), EB67 = f2mul(EB4567, mb45);
        u64 eb[8];
        eb[0] = f2mul(EB01, b[1]); eb[1] = f2mul(EB01, b[0]);
        eb[2] = f2mul(EB23, b[3]); eb[3] = f2mul(EB23, b[2]);
        eb[4] = f2mul(EB45, b[5]); eb[5] = f2mul(EB45, b[4]);
        eb[6] = f2mul(EB67, b[7]); eb[7] = f2mul(EB67, b[6]);

        // D = 0.5*(D1 + Pa + Pb)  (D1 here is 2*sum_{i<j}, so fold 0.5 once)
        u64 D = f2mul(cH, f2add(D1, f2add(Pa, Pb)));
        float Dlo, Dhi; upk(Dlo, Dhi, D);
        u64 rD = pk(rcp_approx(Dlo), rcp_approx(Dhi));

        float op[8], oq[8];
#pragma unroll
        for (int d = 0; d < 8; d++) {
            u64 inner = f2fma(b[d], ea[d], f2mul(a[d], eb[d]));  // carries 1/4
            u64 num   = f2fma(f2mul(a[d], b[d]), eS[d], inner);
            float lo, hi; upk(lo, hi, f2mul(num, rD));
            op[d] = lo; oq[d] = hi;
        }

        o4[2 * p + 0] = make_float4(op[0], op[1], op[2], op[3]);
        o4[2 * p + 1] = make_float4(op[4], op[5], op[6], op[7]);
        o4[2 * q + 0] = make_float4(oq[0], oq[1], oq[2], oq[3]);
        o4[2 * q + 1] = make_float4(oq[4], oq[5], oq[6], oq[7]);
    }
}

extern "C" void kernel_launch(void* const* d_in, const int* in_sizes, int n_in,
                              void* d_out, int out_size) {
    const float4* x4 = (const float4*)d_in[0];   // [N, 8] fp32
    float4* o4 = (float4*)d_out;
    int n = in_sizes[0] / 8;
    int M = (n + 1) / 2;                          // packed pairs (p, p+M)
    const int block = 256;
    int grid = 148 * 2;                           // persistent, 2 CTAs/SM at 128 regs
    int max_grid = (M + block - 1) / block;
    if (grid > max_grid) grid = max_grid;
    int stride = grid * block;
    e8_quantize_kernel<<<grid, block>>>(x4, o4, n, M, stride);
}

// round 6
// speedup vs baseline: 1.1604x; 1.1604x over previous
#include <cuda_runtime.h>

// E8 quantizer, closed form, 2-lane-cooperative (half a point per thread).
//
// Math (rounds 1-5): all 240 E8 roots have ||c||^2 = 2, so the softmax over
// -(dist^2)/T reduces to softmax(beta * x.c), beta = 2/0.3, and factorizes:
//  Type-1 (112 roots, +-1 at i, +-1 at j):  A_i = 2cosh(beta x_i), B_i = 2sinh(beta x_i)
//     denom1 = sum_{i<j} A_i A_j = 0.5 * sum_d A_d * exclSum_d(A)
//     num1_d = B_d * exclSum_d(A),  B_d = a_d * b_d
//  Type-2 (128 roots, (+-1/2)^8 even parity): a_i = 2cosh(bx_i/2), b_i = 2sinh(bx_i/2)
//     denom2 = (prod a + prod b)/2
//     num2_d = ( b_d * exclProd_d(a) + a_d * exclProd_d(b) ) / 4
//  with A = a^2 - 2.  16 EX2 + 1 RCP per point.
//  All-positive adds / sign-safe muls -> no cancellation; +- root pairs =>
//  denom >= 1 => no max-shift needed.
//
// R5 lesson: packing 2 points/thread doubles registers and kills occupancy.
// This round goes the other way: SPLIT one point across a lane pair.
// Lane 2k   owns dims 0-3  (loads x4[g], g = 2k)
// Lane 2k+1 owns dims 4-7  (loads x4[g], g = 2k+1)
// Cross-half coupling is only 4 scalars via __shfl_xor(.,1):
//   S_other (sum of partner A's), Pa_other, Pb_other (partner products),
//   sigma_other (partner's partial of sum_d A_d*eS_d).
// ~35 regs -> 6 CTAs/SM occupancy, loads/stores are exactly x4[g]/o4[g].

#define BETA_HALF_LOG2E 4.8089834696568576f   // (2/0.3)/2 * log2(e)

__device__ __forceinline__ float ex2_approx(float x) {
    float y; asm("ex2.approx.ftz.f32 %0, %1;" : "=f"(y) : "f"(x)); return y;
}
__device__ __forceinline__ float rcp_approx(float x) {
    float y; asm("rcp.approx.ftz.f32 %0, %1;" : "=f"(y) : "f"(x)); return y;
}

__global__ void __launch_bounds__(256) e8_quantize_kernel(
    const float4* __restrict__ x4, float4* __restrict__ o4, int m)
{
    int g = blockIdx.x * blockDim.x + threadIdx.x;   // one float4 (half point)
    if (g >= m) return;   // m % 32 == 0 for N=1M -> warp-uniform exit

    float4 v = x4[g];
    float xi[4] = {v.x, v.y, v.z, v.w};

    // per-dim transcendentals for this half
    float a[4], b[4], A[4];
#pragma unroll
    for (int i = 0; i < 4; i++) {
        float t  = xi[i] * BETA_HALF_LOG2E;
        float hp = ex2_approx(t);
        float hn = ex2_approx(-t);
        a[i] = hp + hn;
        b[i] = hp - hn;
        A[i] = fmaf(a[i], a[i], -2.0f);
    }

    // ---- own-half trees (4 elements each) ----
    // sums of A (all positive)
    float s01 = A[0] + A[1], s23 = A[2] + A[3];
    float Sown = s01 + s23;
    float eo0 = A[1] + s23, eo1 = A[0] + s23;     // exclusive-within-half sums
    float eo2 = s01 + A[3], eo3 = s01 + A[2];

    // products of a
    float pa01 = a[0] * a[1], pa23 = a[2] * a[3];
    float Paown = pa01 * pa23;
    float epa0 = a[1] * pa23, epa1 = a[0] * pa23;
    float epa2 = pa01 * a[3], epa3 = pa01 * a[2];

    // products of b
    float pb01 = b[0] * b[1], pb23 = b[2] * b[3];
    float Pbown = pb01 * pb23;
    float epb0 = b[1] * pb23, epb1 = b[0] * pb23;
    float epb2 = pb01 * b[3], epb3 = pb01 * b[2];

    // ---- partner aggregates (lane pair = one point) ----
    float Soth  = __shfl_xor_sync(0xffffffffu, Sown,  1);
    float Paoth = __shfl_xor_sync(0xffffffffu, Paown, 1);
    float Pboth = __shfl_xor_sync(0xffffffffu, Pbown, 1);

    // full exclusive sums: eS_d = exclusive-own + partner total
    float eS[4] = {eo0 + Soth, eo1 + Soth, eo2 + Soth, eo3 + Soth};

    // sigma = sum over own dims of A_d * eS_d; total over 8 dims = 2*sum_{i<j}A_iA_j
    float sigma = A[0] * eS[0];
    sigma = fmaf(A[1], eS[1], sigma);
    sigma = fmaf(A[2], eS[2], sigma);
    sigma = fmaf(A[3], eS[3], sigma);
    float sig_tot = sigma + __shfl_xor_sync(0xffffffffu, sigma, 1);

    // full exclusive products, 1/4 folded into the partner factor
    float PaQ = Paoth * 0.25f;
    float PbQ = Pboth * 0.25f;
    float ea[4] = {epa0 * PaQ, epa1 * PaQ, epa2 * PaQ, epa3 * PaQ};
    float eb[4] = {epb0 * PbQ, epb1 * PbQ, epb2 * PbQ, epb3 * PbQ};

    // denominator (symmetric in the two halves -> bit-identical on both lanes)
    float PaF = Paown * Paoth;
    float PbF = Pbown * Pboth;
    float D   = 0.5f * (sig_tot + PaF + PbF);
    float rD  = rcp_approx(D);

    float o[4];
#pragma unroll
    for (int d = 0; d < 4; d++) {
        float inner = fmaf(b[d], ea[d], a[d] * eb[d]);     // carries the 1/4
        float num   = fmaf(a[d] * b[d], eS[d], inner);
        o[d] = num * rD;
    }

    o4[g] = make_float4(o[0], o[1], o[2], o[3]);
}

extern "C" void kernel_launch(void* const* d_in, const int* in_sizes, int n_in,
                              void* d_out, int out_size) {
    const float4* x4 = (const float4*)d_in[0];   // [N, 8] fp32 = [2N] float4
    float4* o4 = (float4*)d_out;
    int n = in_sizes[0] / 8;
    int m = 2 * n;                                // half-points (float4 units)
    const int block = 256;
    int grid = (m + block - 1) / block;
    e8_quantize_kernel<<<grid, block>>>(x4, o4, m);
}